// round 1
// baseline (speedup 1.0000x reference)
#include <cuda_runtime.h>

// ---------------------------------------------------------------------------
// MultiheadAttention: out = softmax_causal((XqWq^T+bq)(XkWk^T+bk)^T/sqrt(hd)) (XvWv^T+bv) Wo^T + bo
// B=4, S=2048, D=1024, H=16, hd=64.  All fp32.
// R1 baseline: fp32 SIMT register-tiled GEMMs + flash attention.
// ---------------------------------------------------------------------------

#define D_MODEL 1024
#define NUM_HEAD 16
#define HID_DIM 64
#define BATCH 4
#define SEQ 2048
#define MROWS (BATCH * SEQ)   // 8192

// Scratch (allocation-free: __device__ globals). 4 x 32 MB.
__device__ float g_q[(size_t)MROWS * D_MODEL];
__device__ float g_k[(size_t)MROWS * D_MODEL];
__device__ float g_v[(size_t)MROWS * D_MODEL];
__device__ float g_a[(size_t)MROWS * D_MODEL];

// ---------------------------------------------------------------------------
// GEMM: C[M,N] = A[M,K] @ W[N,K]^T + bias[N]   (torch Linear convention)
// 128x128 block tile, BK=16, 256 threads, 8x8 per-thread micro-tile.
// ---------------------------------------------------------------------------
#define BM 128
#define BN 128
#define BK 16
#define SPAD 4

__global__ __launch_bounds__(256, 2) void gemm_bias_kernel(
    const float* __restrict__ A, const float* __restrict__ W,
    const float* __restrict__ bias, float* __restrict__ C,
    int M, int N, int K)
{
    __shared__ float As[BK][BM + SPAD];
    __shared__ float Bs[BK][BN + SPAD];

    const int tid  = threadIdx.x;
    const int row0 = blockIdx.y * BM;
    const int col0 = blockIdx.x * BN;
    const int trow = (tid >> 4) * 8;   // 0..120
    const int tcol = (tid & 15) * 8;   // 0..120

    float acc[8][8];
    #pragma unroll
    for (int i = 0; i < 8; i++)
        #pragma unroll
        for (int j = 0; j < 8; j++) acc[i][j] = 0.f;

    for (int k0 = 0; k0 < K; k0 += BK) {
        // Load 128x16 tiles of A and W (each 512 float4; 2 per thread per matrix).
        #pragma unroll
        for (int i = 0; i < 2; i++) {
            int idx = tid + (i << 8);          // 0..511
            int r   = idx >> 2;                // 0..127
            int c   = (idx & 3) << 2;          // 0,4,8,12
            float4 av = *reinterpret_cast<const float4*>(
                &A[(size_t)(row0 + r) * K + k0 + c]);
            As[c + 0][r] = av.x; As[c + 1][r] = av.y;
            As[c + 2][r] = av.z; As[c + 3][r] = av.w;
            float4 wv = *reinterpret_cast<const float4*>(
                &W[(size_t)(col0 + r) * K + k0 + c]);
            Bs[c + 0][r] = wv.x; Bs[c + 1][r] = wv.y;
            Bs[c + 2][r] = wv.z; Bs[c + 3][r] = wv.w;
        }
        __syncthreads();

        #pragma unroll
        for (int k = 0; k < BK; k++) {
            float a[8], b[8];
            *(float4*)&a[0] = *(const float4*)&As[k][trow];
            *(float4*)&a[4] = *(const float4*)&As[k][trow + 4];
            *(float4*)&b[0] = *(const float4*)&Bs[k][tcol];
            *(float4*)&b[4] = *(const float4*)&Bs[k][tcol + 4];
            #pragma unroll
            for (int i = 0; i < 8; i++)
                #pragma unroll
                for (int j = 0; j < 8; j++)
                    acc[i][j] = fmaf(a[i], b[j], acc[i][j]);
        }
        __syncthreads();
    }

    #pragma unroll
    for (int i = 0; i < 8; i++) {
        #pragma unroll
        for (int j = 0; j < 8; j += 4) {
            float4 o;
            o.x = acc[i][j + 0] + bias[col0 + tcol + j + 0];
            o.y = acc[i][j + 1] + bias[col0 + tcol + j + 1];
            o.z = acc[i][j + 2] + bias[col0 + tcol + j + 2];
            o.w = acc[i][j + 3] + bias[col0 + tcol + j + 3];
            *reinterpret_cast<float4*>(
                &C[(size_t)(row0 + trow + i) * N + col0 + tcol + j]) = o;
        }
    }
}

// ---------------------------------------------------------------------------
// Flash attention (causal). One thread = one query row. 128 rows per block.
// q/k/v/o layout: [b, s, D_MODEL] with head h at column offset h*HID_DIM.
// ---------------------------------------------------------------------------
#define AQ 128   // query rows per block (== blockDim.x)
#define AK 32    // keys per smem tile

__global__ __launch_bounds__(AQ) void flash_attn_kernel(
    const float* __restrict__ q, const float* __restrict__ k,
    const float* __restrict__ v, float* __restrict__ o)
{
    __shared__ float Ks[AK][HID_DIM];
    __shared__ float Vs[AK][HID_DIM];

    const int qt  = blockIdx.x;
    const int h   = blockIdx.y;
    const int b   = blockIdx.z;
    const int tid = threadIdx.x;
    const int qr  = qt * AQ + tid;
    const size_t base = (size_t)b * SEQ * D_MODEL + (size_t)h * HID_DIM;

    float qreg[HID_DIM];
    {
        const float* qp = q + base + (size_t)qr * D_MODEL;
        #pragma unroll
        for (int d = 0; d < HID_DIM; d += 4)
            *(float4*)&qreg[d] = *(const float4*)&qp[d];
    }
    float acc[HID_DIM];
    #pragma unroll
    for (int d = 0; d < HID_DIM; d++) acc[d] = 0.f;
    float m = -1e30f, l = 0.f;

    const int kend = qt * AQ + AQ;   // causal: no key beyond last row of this q-tile
    for (int kb = 0; kb < kend; kb += AK) {
        __syncthreads();
        // Load AK x 64 K and V tiles (512 float4 each; 4 per thread).
        #pragma unroll
        for (int i = 0; i < 4; i++) {
            int idx = tid + (i << 7);      // 0..511
            int r   = idx >> 4;            // 0..31
            int c   = (idx & 15) << 2;     // 0..60
            const size_t goff = base + (size_t)(kb + r) * D_MODEL + c;
            *(float4*)&Ks[r][c] = *(const float4*)&k[goff];
            *(float4*)&Vs[r][c] = *(const float4*)&v[goff];
        }
        __syncthreads();

        float s[AK];
        #pragma unroll
        for (int j = 0; j < AK; j++) {
            float t = 0.f;
            #pragma unroll
            for (int d = 0; d < HID_DIM; d++)
                t = fmaf(qreg[d], Ks[j][d], t);   // smem broadcast reads
            s[j] = (kb + j <= qr) ? t * 0.125f : -1e30f;
        }

        float tm = m;
        #pragma unroll
        for (int j = 0; j < AK; j++) tm = fmaxf(tm, s[j]);
        float alpha = __expf(m - tm);
        l *= alpha;
        #pragma unroll
        for (int d = 0; d < HID_DIM; d++) acc[d] *= alpha;
        #pragma unroll
        for (int j = 0; j < AK; j++) {
            float p = __expf(s[j] - tm);
            l += p;
            #pragma unroll
            for (int d = 0; d < HID_DIM; d++)
                acc[d] = fmaf(p, Vs[j][d], acc[d]);
        }
        m = tm;
    }

    const float inv = 1.f / l;
    float* op = o + base + (size_t)qr * D_MODEL;
    #pragma unroll
    for (int d = 0; d < HID_DIM; d += 4) {
        float4 ov;
        ov.x = acc[d + 0] * inv; ov.y = acc[d + 1] * inv;
        ov.z = acc[d + 2] * inv; ov.w = acc[d + 3] * inv;
        *(float4*)&op[d] = ov;
    }
}

// ---------------------------------------------------------------------------
// Launch
// ---------------------------------------------------------------------------
extern "C" void kernel_launch(void* const* d_in, const int* in_sizes, int n_in,
                              void* d_out, int out_size)
{
    const float* Q  = (const float*)d_in[0];
    const float* K  = (const float*)d_in[1];
    const float* V  = (const float*)d_in[2];
    const float* Wq = (const float*)d_in[3];
    const float* bq = (const float*)d_in[4];
    const float* Wk = (const float*)d_in[5];
    const float* bk = (const float*)d_in[6];
    const float* Wv = (const float*)d_in[7];
    const float* bv = (const float*)d_in[8];
    const float* Wo = (const float*)d_in[9];
    const float* bo = (const float*)d_in[10];
    float* out = (float*)d_out;

    float *qb, *kb, *vb, *ab;
    cudaGetSymbolAddress((void**)&qb, g_q);
    cudaGetSymbolAddress((void**)&kb, g_k);
    cudaGetSymbolAddress((void**)&vb, g_v);
    cudaGetSymbolAddress((void**)&ab, g_a);

    dim3 ggrid(D_MODEL / BN, MROWS / BM);   // (8, 64)
    gemm_bias_kernel<<<ggrid, 256>>>(Q, Wq, bq, qb, MROWS, D_MODEL, D_MODEL);
    gemm_bias_kernel<<<ggrid, 256>>>(K, Wk, bk, kb, MROWS, D_MODEL, D_MODEL);
    gemm_bias_kernel<<<ggrid, 256>>>(V, Wv, bv, vb, MROWS, D_MODEL, D_MODEL);

    flash_attn_kernel<<<dim3(SEQ / AQ, NUM_HEAD, BATCH), AQ>>>(qb, kb, vb, ab);

    gemm_bias_kernel<<<ggrid, 256>>>(ab, Wo, bo, out, MROWS, D_MODEL, D_MODEL);
}

// round 2
// speedup vs baseline: 1.5026x; 1.5026x over previous
#include <cuda_runtime.h>
#include <cstdint>

// ---------------------------------------------------------------------------
// MultiheadAttention  B=4, S=2048, D=1024, H=16, hd=64, causal, fp32.
// R2: tf32 mma.sync GEMMs (cp.async double-buffered) + float4-vectorized flash.
// ---------------------------------------------------------------------------

#define D_MODEL 1024
#define NUM_HEAD 16
#define HID_DIM 64
#define BATCH 4
#define SEQ 2048
#define MROWS (BATCH * SEQ)   // 8192

__device__ float g_q[(size_t)MROWS * D_MODEL];
__device__ float g_k[(size_t)MROWS * D_MODEL];
__device__ float g_v[(size_t)MROWS * D_MODEL];
__device__ float g_a[(size_t)MROWS * D_MODEL];

// ---------------------------------------------------------------------------
// tf32 tensor-core GEMM:  C[M,N] = A[M,K] @ W[N,K]^T + bias[N]
// BM=BN=128, BK=16, 256 threads (8 warps, 2x4), warp tile 64x32,
// mma.sync.m16n8k8.tf32, cp.async 2-stage pipeline.
// ---------------------------------------------------------------------------
#define BM 128
#define BN 128
#define BK 16
#define LDK 20          // BK + 4 pad: frag LDS conflict-free
#define GTHREADS 256
#define KTILES (D_MODEL / BK)   // 64

__device__ __forceinline__ uint32_t f2tf32(float f) {
    uint32_t r;
    asm volatile("cvt.rna.tf32.f32 %0, %1;" : "=r"(r) : "f"(f));
    return r;
}
__device__ __forceinline__ void cp_async16(uint32_t saddr, const void* gptr) {
    asm volatile("cp.async.cg.shared.global [%0], [%1], 16;\n" :: "r"(saddr), "l"(gptr));
}
__device__ __forceinline__ void cp_commit() {
    asm volatile("cp.async.commit_group;\n");
}

struct GemmArgs {
    const float* A; const float* W; const float* bias; float* C;
};

__global__ __launch_bounds__(GTHREADS) void gemm_tf32_kernel(
    const float* __restrict__ A0, const float* __restrict__ W0,
    const float* __restrict__ b0, float* __restrict__ C0,
    const float* __restrict__ A1, const float* __restrict__ W1,
    const float* __restrict__ b1, float* __restrict__ C1,
    const float* __restrict__ A2, const float* __restrict__ W2,
    const float* __restrict__ b2, float* __restrict__ C2)
{
    __shared__ float As[2][BM][LDK];
    __shared__ float Ws[2][BN][LDK];

    const float* A; const float* W; const float* bias; float* C;
    if (blockIdx.z == 0)      { A = A0; W = W0; bias = b0; C = C0; }
    else if (blockIdx.z == 1) { A = A1; W = W1; bias = b1; C = C1; }
    else                      { A = A2; W = W2; bias = b2; C = C2; }

    const int tid  = threadIdx.x;
    const int row0 = blockIdx.y * BM;
    const int col0 = blockIdx.x * BN;
    const int K    = D_MODEL, N = D_MODEL;

    const int wid    = tid >> 5;
    const int lane   = tid & 31;
    const int warp_m = (wid & 1) * 64;   // 2 warps along M
    const int warp_n = (wid >> 1) * 32;  // 4 warps along N
    const int grp    = lane >> 2;        // 0..7
    const int qid    = lane & 3;         // 0..3

    // global load mapping (per stage: 512 float4 per matrix, 2 per thread)
    const int lr  = tid >> 2;            // 0..63  (two rows handled: lr, lr+64)
    const int lc  = (tid & 3) << 2;      // 0,4,8,12

    float acc[4][4][4];
    #pragma unroll
    for (int i = 0; i < 4; i++)
        #pragma unroll
        for (int j = 0; j < 4; j++)
            #pragma unroll
            for (int c = 0; c < 4; c++) acc[i][j][c] = 0.f;

    auto load_stage = [&](int st, int k0) {
        #pragma unroll
        for (int h = 0; h < 2; h++) {
            int r = lr + h * 64;
            cp_async16((uint32_t)__cvta_generic_to_shared(&As[st][r][lc]),
                       &A[(size_t)(row0 + r) * K + k0 + lc]);
            cp_async16((uint32_t)__cvta_generic_to_shared(&Ws[st][r][lc]),
                       &W[(size_t)(col0 + r) * K + k0 + lc]);
        }
        cp_commit();
    };

    load_stage(0, 0);

    for (int t = 0; t < KTILES; t++) {
        const int st = t & 1;
        if (t + 1 < KTILES) {
            load_stage(st ^ 1, (t + 1) * BK);
            asm volatile("cp.async.wait_group 1;\n");
        } else {
            asm volatile("cp.async.wait_group 0;\n");
        }
        __syncthreads();

        #pragma unroll
        for (int ks = 0; ks < BK; ks += 8) {
            uint32_t af[4][4], bf[4][2];
            #pragma unroll
            for (int i = 0; i < 4; i++) {
                int r = warp_m + i * 16 + grp;
                af[i][0] = f2tf32(As[st][r    ][ks + qid    ]);
                af[i][1] = f2tf32(As[st][r + 8][ks + qid    ]);
                af[i][2] = f2tf32(As[st][r    ][ks + qid + 4]);
                af[i][3] = f2tf32(As[st][r + 8][ks + qid + 4]);
            }
            #pragma unroll
            for (int j = 0; j < 4; j++) {
                int n = warp_n + j * 8 + grp;
                bf[j][0] = f2tf32(Ws[st][n][ks + qid    ]);
                bf[j][1] = f2tf32(Ws[st][n][ks + qid + 4]);
            }
            #pragma unroll
            for (int i = 0; i < 4; i++)
                #pragma unroll
                for (int j = 0; j < 4; j++) {
                    asm volatile(
                        "mma.sync.aligned.m16n8k8.row.col.f32.tf32.tf32.f32 "
                        "{%0,%1,%2,%3}, {%4,%5,%6,%7}, {%8,%9}, {%0,%1,%2,%3};\n"
                        : "+f"(acc[i][j][0]), "+f"(acc[i][j][1]),
                          "+f"(acc[i][j][2]), "+f"(acc[i][j][3])
                        : "r"(af[i][0]), "r"(af[i][1]), "r"(af[i][2]), "r"(af[i][3]),
                          "r"(bf[j][0]), "r"(bf[j][1]));
                }
        }
        __syncthreads();
    }

    // epilogue: c0,c1 at (row, 2*qid), c2,c3 at (row+8, 2*qid)
    #pragma unroll
    for (int i = 0; i < 4; i++) {
        int r = row0 + warp_m + i * 16 + grp;
        #pragma unroll
        for (int j = 0; j < 4; j++) {
            int cidx = col0 + warp_n + j * 8 + qid * 2;
            float bx = bias[cidx], by = bias[cidx + 1];
            float2 o0 = make_float2(acc[i][j][0] + bx, acc[i][j][1] + by);
            float2 o1 = make_float2(acc[i][j][2] + bx, acc[i][j][3] + by);
            *reinterpret_cast<float2*>(&C[(size_t)r * N + cidx])       = o0;
            *reinterpret_cast<float2*>(&C[(size_t)(r + 8) * N + cidx]) = o1;
        }
    }
}

// ---------------------------------------------------------------------------
// Flash attention (causal). One thread = one query row, float4 LDS.
// ---------------------------------------------------------------------------
#define AQ 128
#define AK 32

__global__ __launch_bounds__(AQ) void flash_attn_kernel(
    const float* __restrict__ q, const float* __restrict__ k,
    const float* __restrict__ v, float* __restrict__ o)
{
    __shared__ float Ks[AK][HID_DIM];
    __shared__ float Vs[AK][HID_DIM];

    const int qt  = blockIdx.x;
    const int h   = blockIdx.y;
    const int b   = blockIdx.z;
    const int tid = threadIdx.x;
    const int qr  = qt * AQ + tid;
    const size_t base = (size_t)b * SEQ * D_MODEL + (size_t)h * HID_DIM;

    float qreg[HID_DIM];
    {
        const float* qp = q + base + (size_t)qr * D_MODEL;
        #pragma unroll
        for (int d = 0; d < HID_DIM; d += 4)
            *(float4*)&qreg[d] = *(const float4*)&qp[d];
    }
    float acc[HID_DIM];
    #pragma unroll
    for (int d = 0; d < HID_DIM; d++) acc[d] = 0.f;
    float m = -1e30f, l = 0.f;

    const int kend = qt * AQ + AQ;
    for (int kb = 0; kb < kend; kb += AK) {
        __syncthreads();
        #pragma unroll
        for (int i = 0; i < 4; i++) {
            int idx = tid + (i << 7);
            int r   = idx >> 4;
            int c   = (idx & 15) << 2;
            const size_t goff = base + (size_t)(kb + r) * D_MODEL + c;
            *(float4*)&Ks[r][c] = *(const float4*)&k[goff];
            *(float4*)&Vs[r][c] = *(const float4*)&v[goff];
        }
        __syncthreads();

        const bool full = (kb + AK - 1) <= qr;   // no masking needed in tile
        float s[AK];
        #pragma unroll
        for (int j = 0; j < AK; j++) {
            float t = 0.f;
            const float4* kp = reinterpret_cast<const float4*>(&Ks[j][0]);
            #pragma unroll
            for (int d4 = 0; d4 < HID_DIM / 4; d4++) {
                float4 kv = kp[d4];
                t = fmaf(qreg[4 * d4 + 0], kv.x, t);
                t = fmaf(qreg[4 * d4 + 1], kv.y, t);
                t = fmaf(qreg[4 * d4 + 2], kv.z, t);
                t = fmaf(qreg[4 * d4 + 3], kv.w, t);
            }
            s[j] = (full || (kb + j <= qr)) ? t * 0.125f : -1e30f;
        }

        float tm = m;
        #pragma unroll
        for (int j = 0; j < AK; j++) tm = fmaxf(tm, s[j]);
        float alpha = __expf(m - tm);
        l *= alpha;
        #pragma unroll
        for (int d = 0; d < HID_DIM; d++) acc[d] *= alpha;
        #pragma unroll
        for (int j = 0; j < AK; j++) {
            float p = __expf(s[j] - tm);
            l += p;
            const float4* vp = reinterpret_cast<const float4*>(&Vs[j][0]);
            #pragma unroll
            for (int d4 = 0; d4 < HID_DIM / 4; d4++) {
                float4 vv = vp[d4];
                acc[4 * d4 + 0] = fmaf(p, vv.x, acc[4 * d4 + 0]);
                acc[4 * d4 + 1] = fmaf(p, vv.y, acc[4 * d4 + 1]);
                acc[4 * d4 + 2] = fmaf(p, vv.z, acc[4 * d4 + 2]);
                acc[4 * d4 + 3] = fmaf(p, vv.w, acc[4 * d4 + 3]);
            }
        }
        m = tm;
    }

    const float inv = 1.f / l;
    float* op = o + base + (size_t)qr * D_MODEL;
    #pragma unroll
    for (int d = 0; d < HID_DIM; d += 4) {
        float4 ov;
        ov.x = acc[d + 0] * inv; ov.y = acc[d + 1] * inv;
        ov.z = acc[d + 2] * inv; ov.w = acc[d + 3] * inv;
        *(float4*)&op[d] = ov;
    }
}

// ---------------------------------------------------------------------------
extern "C" void kernel_launch(void* const* d_in, const int* in_sizes, int n_in,
                              void* d_out, int out_size)
{
    const float* Q  = (const float*)d_in[0];
    const float* K  = (const float*)d_in[1];
    const float* V  = (const float*)d_in[2];
    const float* Wq = (const float*)d_in[3];
    const float* bq = (const float*)d_in[4];
    const float* Wk = (const float*)d_in[5];
    const float* bk = (const float*)d_in[6];
    const float* Wv = (const float*)d_in[7];
    const float* bv = (const float*)d_in[8];
    const float* Wo = (const float*)d_in[9];
    const float* bo = (const float*)d_in[10];
    float* out = (float*)d_out;

    float *qb, *kb, *vb, *ab;
    cudaGetSymbolAddress((void**)&qb, g_q);
    cudaGetSymbolAddress((void**)&kb, g_k);
    cudaGetSymbolAddress((void**)&vb, g_v);
    cudaGetSymbolAddress((void**)&ab, g_a);

    // fused QKV projections: one launch, z selects the problem
    dim3 qkv_grid(D_MODEL / BN, MROWS / BM, 3);
    gemm_tf32_kernel<<<qkv_grid, GTHREADS>>>(
        Q, Wq, bq, qb,
        K, Wk, bk, kb,
        V, Wv, bv, vb);

    flash_attn_kernel<<<dim3(SEQ / AQ, NUM_HEAD, BATCH), AQ>>>(qb, kb, vb, ab);

    dim3 o_grid(D_MODEL / BN, MROWS / BM, 1);
    gemm_tf32_kernel<<<o_grid, GTHREADS>>>(
        ab, Wo, bo, out,
        ab, Wo, bo, out,
        ab, Wo, bo, out);
}

// round 7
// speedup vs baseline: 3.8357x; 2.5527x over previous
#include <cuda_runtime.h>
#include <cstdint>

// ---------------------------------------------------------------------------
// MultiheadAttention  B=4, S=2048, D=1024, H=16, hd=64, causal, fp32.
// R7 = R6 resubmit (container infra failure):
//   tf32 mma GEMMs + tf32 mma flash attention,
//   causal-mask predicate fix (kb+FK-1 > wrow0), l from tf32-quantized p.
// ---------------------------------------------------------------------------

#define D_MODEL 1024
#define NUM_HEAD 16
#define HID_DIM 64
#define BATCH 4
#define SEQ 2048
#define MROWS (BATCH * SEQ)   // 8192

__device__ float g_q[(size_t)MROWS * D_MODEL];
__device__ float g_k[(size_t)MROWS * D_MODEL];
__device__ float g_v[(size_t)MROWS * D_MODEL];
__device__ float g_a[(size_t)MROWS * D_MODEL];

__device__ __forceinline__ uint32_t f2tf32(float f) {
    uint32_t r;
    asm volatile("cvt.rna.tf32.f32 %0, %1;" : "=r"(r) : "f"(f));
    return r;
}
__device__ __forceinline__ void cp_async16(uint32_t saddr, const void* gptr) {
    asm volatile("cp.async.cg.shared.global [%0], [%1], 16;\n" :: "r"(saddr), "l"(gptr));
}
__device__ __forceinline__ void cp_commit() {
    asm volatile("cp.async.commit_group;\n");
}
__device__ __forceinline__ void mma_tf32(
    float& d0, float& d1, float& d2, float& d3,
    uint32_t a0, uint32_t a1, uint32_t a2, uint32_t a3,
    uint32_t b0, uint32_t b1)
{
    asm volatile(
        "mma.sync.aligned.m16n8k8.row.col.f32.tf32.tf32.f32 "
        "{%0,%1,%2,%3}, {%4,%5,%6,%7}, {%8,%9}, {%0,%1,%2,%3};\n"
        : "+f"(d0), "+f"(d1), "+f"(d2), "+f"(d3)
        : "r"(a0), "r"(a1), "r"(a2), "r"(a3), "r"(b0), "r"(b1));
}

// ---------------------------------------------------------------------------
// tf32 GEMM: C[M,N] = A[M,K] @ W[N,K]^T + bias
// ---------------------------------------------------------------------------
#define BM 128
#define BN 128
#define BK 16
#define LDK 20
#define GTHREADS 256
#define KTILES (D_MODEL / BK)

__global__ __launch_bounds__(GTHREADS) void gemm_tf32_kernel(
    const float* __restrict__ A0, const float* __restrict__ W0,
    const float* __restrict__ b0, float* __restrict__ C0,
    const float* __restrict__ A1, const float* __restrict__ W1,
    const float* __restrict__ b1, float* __restrict__ C1,
    const float* __restrict__ A2, const float* __restrict__ W2,
    const float* __restrict__ b2, float* __restrict__ C2)
{
    __shared__ float As[2][BM][LDK];
    __shared__ float Ws[2][BN][LDK];

    const float* A; const float* W; const float* bias; float* C;
    if (blockIdx.z == 0)      { A = A0; W = W0; bias = b0; C = C0; }
    else if (blockIdx.z == 1) { A = A1; W = W1; bias = b1; C = C1; }
    else                      { A = A2; W = W2; bias = b2; C = C2; }

    const int tid  = threadIdx.x;
    const int row0 = blockIdx.y * BM;
    const int col0 = blockIdx.x * BN;
    const int K    = D_MODEL, N = D_MODEL;

    const int wid    = tid >> 5;
    const int lane   = tid & 31;
    const int warp_m = (wid & 1) * 64;
    const int warp_n = (wid >> 1) * 32;
    const int grp    = lane >> 2;
    const int qid    = lane & 3;
    const int lr     = tid >> 2;
    const int lc     = (tid & 3) << 2;

    float acc[4][4][4];
    #pragma unroll
    for (int i = 0; i < 4; i++)
        #pragma unroll
        for (int j = 0; j < 4; j++)
            #pragma unroll
            for (int c = 0; c < 4; c++) acc[i][j][c] = 0.f;

    auto load_stage = [&](int st, int k0) {
        #pragma unroll
        for (int h = 0; h < 2; h++) {
            int r = lr + h * 64;
            cp_async16((uint32_t)__cvta_generic_to_shared(&As[st][r][lc]),
                       &A[(size_t)(row0 + r) * K + k0 + lc]);
            cp_async16((uint32_t)__cvta_generic_to_shared(&Ws[st][r][lc]),
                       &W[(size_t)(col0 + r) * K + k0 + lc]);
        }
        cp_commit();
    };

    load_stage(0, 0);

    for (int t = 0; t < KTILES; t++) {
        const int st = t & 1;
        if (t + 1 < KTILES) {
            load_stage(st ^ 1, (t + 1) * BK);
            asm volatile("cp.async.wait_group 1;\n");
        } else {
            asm volatile("cp.async.wait_group 0;\n");
        }
        __syncthreads();

        #pragma unroll
        for (int ks = 0; ks < BK; ks += 8) {
            uint32_t af[4][4], bf[4][2];
            #pragma unroll
            for (int i = 0; i < 4; i++) {
                int r = warp_m + i * 16 + grp;
                af[i][0] = f2tf32(As[st][r    ][ks + qid    ]);
                af[i][1] = f2tf32(As[st][r + 8][ks + qid    ]);
                af[i][2] = f2tf32(As[st][r    ][ks + qid + 4]);
                af[i][3] = f2tf32(As[st][r + 8][ks + qid + 4]);
            }
            #pragma unroll
            for (int j = 0; j < 4; j++) {
                int n = warp_n + j * 8 + grp;
                bf[j][0] = f2tf32(Ws[st][n][ks + qid    ]);
                bf[j][1] = f2tf32(Ws[st][n][ks + qid + 4]);
            }
            #pragma unroll
            for (int i = 0; i < 4; i++)
                #pragma unroll
                for (int j = 0; j < 4; j++)
                    mma_tf32(acc[i][j][0], acc[i][j][1], acc[i][j][2], acc[i][j][3],
                             af[i][0], af[i][1], af[i][2], af[i][3],
                             bf[j][0], bf[j][1]);
        }
        __syncthreads();
    }

    #pragma unroll
    for (int i = 0; i < 4; i++) {
        int r = row0 + warp_m + i * 16 + grp;
        #pragma unroll
        for (int j = 0; j < 4; j++) {
            int cidx = col0 + warp_n + j * 8 + qid * 2;
            float bx = bias[cidx], by = bias[cidx + 1];
            float2 o0 = make_float2(acc[i][j][0] + bx, acc[i][j][1] + by);
            float2 o1 = make_float2(acc[i][j][2] + bx, acc[i][j][3] + by);
            *reinterpret_cast<float2*>(&C[(size_t)r * N + cidx])       = o0;
            *reinterpret_cast<float2*>(&C[(size_t)(r + 8) * N + cidx]) = o1;
        }
    }
}

// ---------------------------------------------------------------------------
// Tensor-core flash attention (causal, tf32 mma).
// CTA: 256 threads = 8 warps; 128 q-rows per CTA, 16 per warp.
// Key tiles of 64, cp.async double-buffered K/V.
// ---------------------------------------------------------------------------
#define FQ 128
#define FK 64
#define LDS_STRIDE 68
#define KV_WORDS (2 * FK * LDS_STRIDE)
#define PS_WORDS (8 * 16 * LDS_STRIDE)
#define FLASH_SMEM_BYTES ((2 * KV_WORDS + PS_WORDS) * 4)   // 104448

__global__ __launch_bounds__(256, 1) void flash_attn_tc_kernel(
    const float* __restrict__ q, const float* __restrict__ k,
    const float* __restrict__ v, float* __restrict__ o)
{
    extern __shared__ float sm[];
    float* Ks = sm;                       // [2][FK][LDS_STRIDE]
    float* Vs = sm + KV_WORDS;            // [2][FK][LDS_STRIDE]
    float* Ps = sm + 2 * KV_WORDS;        // [8][16][LDS_STRIDE]

    const int qt  = blockIdx.x;
    const int h   = blockIdx.y;
    const int b   = blockIdx.z;
    const int tid = threadIdx.x;
    const int w   = tid >> 5;
    const int lane = tid & 31;
    const int grp = lane >> 2;
    const int qid = lane & 3;

    const int q0 = qt * FQ;
    const size_t base = (size_t)b * SEQ * D_MODEL + (size_t)h * HID_DIM;
    const int wrow0 = q0 + w * 16;
    const int wlast = wrow0 + 15;

    uint32_t qf[8][4];
    {
        const float* Qp = q + base + (size_t)wrow0 * D_MODEL;
        #pragma unroll
        for (int ks = 0; ks < 8; ks++) {
            int c = ks * 8 + qid;
            qf[ks][0] = f2tf32(0.125f * Qp[(size_t)grp       * D_MODEL + c]);
            qf[ks][1] = f2tf32(0.125f * Qp[(size_t)(grp + 8) * D_MODEL + c]);
            qf[ks][2] = f2tf32(0.125f * Qp[(size_t)grp       * D_MODEL + c + 4]);
            qf[ks][3] = f2tf32(0.125f * Qp[(size_t)(grp + 8) * D_MODEL + c + 4]);
        }
    }

    float oacc[8][4];
    #pragma unroll
    for (int j = 0; j < 8; j++)
        #pragma unroll
        for (int c = 0; c < 4; c++) oacc[j][c] = 0.f;
    float m0 = -1e30f, m1 = -1e30f, l0 = 0.f, l1 = 0.f;

    float* Pw = Ps + w * 16 * LDS_STRIDE;
    const int nt = 2 * (qt + 1);

    auto load_tile = [&](int st, int kb) {
        float* Kd = Ks + st * FK * LDS_STRIDE;
        float* Vd = Vs + st * FK * LDS_STRIDE;
        #pragma unroll
        for (int i = 0; i < 4; i++) {
            int idx = tid + (i << 8);
            int r   = idx >> 4;
            int c   = (idx & 15) << 2;
            const size_t goff = base + (size_t)(kb + r) * D_MODEL + c;
            cp_async16((uint32_t)__cvta_generic_to_shared(&Kd[r * LDS_STRIDE + c]), &k[goff]);
            cp_async16((uint32_t)__cvta_generic_to_shared(&Vd[r * LDS_STRIDE + c]), &v[goff]);
        }
        cp_commit();
    };

    load_tile(0, 0);

    for (int t = 0; t < nt; t++) {
        const int st = t & 1;
        const int kb = t * FK;
        if (t + 1 < nt) {
            load_tile(st ^ 1, kb + FK);
            asm volatile("cp.async.wait_group 1;\n");
        } else {
            asm volatile("cp.async.wait_group 0;\n");
        }
        __syncthreads();

        if (kb <= wlast) {
            const float* Kt = Ks + st * FK * LDS_STRIDE;
            const float* Vt = Vs + st * FK * LDS_STRIDE;

            float sacc[8][4];
            #pragma unroll
            for (int j = 0; j < 8; j++)
                #pragma unroll
                for (int c = 0; c < 4; c++) sacc[j][c] = 0.f;

            #pragma unroll
            for (int ks = 0; ks < 8; ks++) {
                #pragma unroll
                for (int jn = 0; jn < 8; jn++) {
                    int n = jn * 8 + grp;
                    uint32_t bf0 = f2tf32(Kt[n * LDS_STRIDE + ks * 8 + qid]);
                    uint32_t bf1 = f2tf32(Kt[n * LDS_STRIDE + ks * 8 + qid + 4]);
                    mma_tf32(sacc[jn][0], sacc[jn][1], sacc[jn][2], sacc[jn][3],
                             qf[ks][0], qf[ks][1], qf[ks][2], qf[ks][3], bf0, bf1);
                }
            }

            // causal mask: needed whenever the tile's last column can exceed
            // the warp's FIRST row (R5 bug compared against last row).
            if (kb + FK - 1 > wrow0) {
                const int r0g = wrow0 + grp, r1g = wrow0 + grp + 8;
                #pragma unroll
                for (int jn = 0; jn < 8; jn++) {
                    int c0 = kb + jn * 8 + 2 * qid;
                    if (c0     > r0g) sacc[jn][0] = -1e30f;
                    if (c0 + 1 > r0g) sacc[jn][1] = -1e30f;
                    if (c0     > r1g) sacc[jn][2] = -1e30f;
                    if (c0 + 1 > r1g) sacc[jn][3] = -1e30f;
                }
            }

            float mt0 = -1e30f, mt1 = -1e30f;
            #pragma unroll
            for (int jn = 0; jn < 8; jn++) {
                mt0 = fmaxf(mt0, fmaxf(sacc[jn][0], sacc[jn][1]));
                mt1 = fmaxf(mt1, fmaxf(sacc[jn][2], sacc[jn][3]));
            }
            mt0 = fmaxf(mt0, __shfl_xor_sync(0xffffffffu, mt0, 1));
            mt0 = fmaxf(mt0, __shfl_xor_sync(0xffffffffu, mt0, 2));
            mt1 = fmaxf(mt1, __shfl_xor_sync(0xffffffffu, mt1, 1));
            mt1 = fmaxf(mt1, __shfl_xor_sync(0xffffffffu, mt1, 2));

            float mn0 = fmaxf(m0, mt0), mn1 = fmaxf(m1, mt1);
            float a0 = __expf(m0 - mn0), a1 = __expf(m1 - mn1);
            m0 = mn0; m1 = mn1;
            l0 *= a0; l1 *= a1;
            #pragma unroll
            for (int jn = 0; jn < 8; jn++) {
                oacc[jn][0] *= a0; oacc[jn][1] *= a0;
                oacc[jn][2] *= a1; oacc[jn][3] *= a1;
            }

            #pragma unroll
            for (int jn = 0; jn < 8; jn++) {
                // quantize p to tf32 FIRST, accumulate l from the quantized
                // values: PV numerator and softmax denominator stay consistent.
                float p00 = __uint_as_float(f2tf32(__expf(sacc[jn][0] - mn0)));
                float p01 = __uint_as_float(f2tf32(__expf(sacc[jn][1] - mn0)));
                float p10 = __uint_as_float(f2tf32(__expf(sacc[jn][2] - mn1)));
                float p11 = __uint_as_float(f2tf32(__expf(sacc[jn][3] - mn1)));
                l0 += p00 + p01;
                l1 += p10 + p11;
                int c = jn * 8 + 2 * qid;
                *reinterpret_cast<float2*>(&Pw[grp       * LDS_STRIDE + c]) =
                    make_float2(p00, p01);
                *reinterpret_cast<float2*>(&Pw[(grp + 8) * LDS_STRIDE + c]) =
                    make_float2(p10, p11);
            }
            __syncwarp();

            const uint32_t* Pu = reinterpret_cast<const uint32_t*>(Pw);
            #pragma unroll
            for (int ks = 0; ks < 8; ks++) {
                uint32_t af0 = Pu[grp       * LDS_STRIDE + ks * 8 + qid];
                uint32_t af1 = Pu[(grp + 8) * LDS_STRIDE + ks * 8 + qid];
                uint32_t af2 = Pu[grp       * LDS_STRIDE + ks * 8 + qid + 4];
                uint32_t af3 = Pu[(grp + 8) * LDS_STRIDE + ks * 8 + qid + 4];
                #pragma unroll
                for (int jn = 0; jn < 8; jn++) {
                    int n = jn * 8 + grp;
                    uint32_t bf0 = f2tf32(Vt[(ks * 8 + qid)     * LDS_STRIDE + n]);
                    uint32_t bf1 = f2tf32(Vt[(ks * 8 + qid + 4) * LDS_STRIDE + n]);
                    mma_tf32(oacc[jn][0], oacc[jn][1], oacc[jn][2], oacc[jn][3],
                             af0, af1, af2, af3, bf0, bf1);
                }
            }
        }
        __syncthreads();
    }

    l0 += __shfl_xor_sync(0xffffffffu, l0, 1);
    l0 += __shfl_xor_sync(0xffffffffu, l0, 2);
    l1 += __shfl_xor_sync(0xffffffffu, l1, 1);
    l1 += __shfl_xor_sync(0xffffffffu, l1, 2);
    const float inv0 = 1.f / l0, inv1 = 1.f / l1;

    float* Op = o + base + (size_t)wrow0 * D_MODEL;
    #pragma unroll
    for (int jn = 0; jn < 8; jn++) {
        int c = jn * 8 + 2 * qid;
        float2 o0 = make_float2(oacc[jn][0] * inv0, oacc[jn][1] * inv0);
        float2 o1 = make_float2(oacc[jn][2] * inv1, oacc[jn][3] * inv1);
        *reinterpret_cast<float2*>(&Op[(size_t)grp       * D_MODEL + c]) = o0;
        *reinterpret_cast<float2*>(&Op[(size_t)(grp + 8) * D_MODEL + c]) = o1;
    }
}

// ---------------------------------------------------------------------------
extern "C" void kernel_launch(void* const* d_in, const int* in_sizes, int n_in,
                              void* d_out, int out_size)
{
    const float* Q  = (const float*)d_in[0];
    const float* K  = (const float*)d_in[1];
    const float* V  = (const float*)d_in[2];
    const float* Wq = (const float*)d_in[3];
    const float* bq = (const float*)d_in[4];
    const float* Wk = (const float*)d_in[5];
    const float* bk = (const float*)d_in[6];
    const float* Wv = (const float*)d_in[7];
    const float* bv = (const float*)d_in[8];
    const float* Wo = (const float*)d_in[9];
    const float* bo = (const float*)d_in[10];
    float* out = (float*)d_out;

    float *qb, *kb, *vb, *ab;
    cudaGetSymbolAddress((void**)&qb, g_q);
    cudaGetSymbolAddress((void**)&kb, g_k);
    cudaGetSymbolAddress((void**)&vb, g_v);
    cudaGetSymbolAddress((void**)&ab, g_a);

    cudaFuncSetAttribute(flash_attn_tc_kernel,
                         cudaFuncAttributeMaxDynamicSharedMemorySize,
                         FLASH_SMEM_BYTES);

    dim3 qkv_grid(D_MODEL / BN, MROWS / BM, 3);
    gemm_tf32_kernel<<<qkv_grid, GTHREADS>>>(
        Q, Wq, bq, qb,
        K, Wk, bk, kb,
        V, Wv, bv, vb);

    flash_attn_tc_kernel<<<dim3(SEQ / FQ, NUM_HEAD, BATCH), 256,
                           FLASH_SMEM_BYTES>>>(qb, kb, vb, ab);

    dim3 o_grid(D_MODEL / BN, MROWS / BM, 1);
    gemm_tf32_kernel<<<o_grid, GTHREADS>>>(
        ab, Wo, bo, out,
        ab, Wo, bo, out,
        ab, Wo, bo, out);
}